// round 13
// baseline (speedup 1.0000x reference)
#include <cuda_runtime.h>
#include <cuda_fp16.h>
#include <math.h>

#define Bc  64
#define Sc  512
#define Tc  256
#define Ec  512
#define Hc  512
#define KQc 256
#define Vc  1000
#define BH  (Bc*Hc)
#define NBLK 128
#define NTHR 512

typedef unsigned long long u64t;

// k-paired transposed activation index: aP[(j>>1)*128 + b*2 + (j&1)]
#define PIDX(j,b) ((((j)>>1)<<7) + ((b)<<1) + ((j)&1))

// ---------------- dynamic smem layout (float offsets) ----------------
#define OFF_W0    0                      // A-blocks: Whh1 32x516 ; B-blocks: Wemb 16x516
#define OFF_WL2H  16512                  // Whh2 16x516
#define OFF_WL2X  24768                  // Wih2 16x516
#define OFF_WHID  33024                  // W1 4x1028 (full K=1024)
#define OFF_AB    37136                  // attn struct + precompute tiles
#define OFF_RED   45840                  // reduction 128x66
#define OFF_SS    (OFF_RED + 8320)       // 128 merge scales
#define SMEM_F    54288
#define SMEM_BYTES (SMEM_F * 4)          // 217152 B

// ---------------- device scratch ----------------
__device__ float  g_ktmp[(size_t)Bc*Sc*KQc];   // K fp32 (precompute temp)
__device__ __half g_kk[(size_t)Bc*Sc*Ec];      // KK = K @ Wq  [B*S, 512] fp16
__device__ float  g_c0[(size_t)Bc*Sc];         // bq . k
__device__ __half g_vh[(size_t)Bc*Sc*Ec];      // V cache fp16
__device__ float  g_emb1[(size_t)Vc*4*Hc];     // token -> LSTM1 x-side gate preacts
__device__ __align__(16) float g_h1P[2*BH];    // h1 transposed k-paired, double-buffered
__device__ __align__(16) float g_h2P[2*BH];
__device__ __align__(16) float g_c1T[2*BH];    // c transposed [j][b]
__device__ __align__(16) float g_c2T[2*BH];
__device__ __align__(16) float g_hidP[BH];     // hid transposed k-paired
__device__ __align__(16) float g_ctxpP[2*(size_t)Bc*Ec];  // ctx partials k-paired [half]
__device__ float2 g_mz[2*Bc];                  // per (b,half): {m_local, Z_local}
__device__ float  g_attn_dummy[Bc*Sc];

// ---------------- grid barrier: all-poll (replay-safe) ----------------
__device__ volatile unsigned g_flags[NBLK*32];

__device__ __forceinline__ void gsync(unsigned gen) {
    __syncthreads();
    if (threadIdx.x == 0) {
        __threadfence();
        g_flags[blockIdx.x * 32] = gen;
    }
    if (threadIdx.x < NBLK) {
        while (g_flags[threadIdx.x * 32] < gen) { }
        __threadfence();
    }
    __syncthreads();
}

// ---------------- f32x2 packed FMA ----------------
__device__ __forceinline__ u64t fma2(u64t a, u64t b, u64t c) {
    u64t d;
    asm("fma.rn.f32x2 %0, %1, %2, %3;" : "=l"(d) : "l"(a), "l"(b), "l"(c));
    return d;
}
__device__ __forceinline__ float hsum2(u64t v) {
    return __uint_as_float((unsigned)v) + __uint_as_float((unsigned)(v >> 32));
}
__device__ __forceinline__ u64t pack2(float lo, float hi) {
    u64t d;
    asm("mov.b64 %0, {%1, %2};" : "=l"(d) : "r"(__float_as_uint(lo)), "r"(__float_as_uint(hi)));
    return d;
}
__device__ __forceinline__ u64t dup2(float x) { return pack2(x, x); }

// ---------------- pipelined unstaged GEMM core ----------------
// warp = (rg, kh): kh = warp % NKH, rg = warp / NKH; NKH = 16/(NROWS/NRPT).
// Thread: W rows rg*NRPT.., batches (lane, lane+32), k-slice kh.
// Explicit cur/next register rotation on the L2 A-loads (latency hiding).
template<int NROWS, int NRPT, int KTOT, bool DUAL>
__device__ __forceinline__ void mm_pipe(u64t (*acc)[2],
                                        const float* __restrict__ aP0,
                                        const float* __restrict__ aP1,
                                        const float* __restrict__ w0sm,
                                        const float* __restrict__ w1sm, int padw) {
    const int NRG = NROWS / NRPT;
    const int NKH = 16 / NRG;
    const int KT = KTOT / NKH;
    int warp = threadIdx.x >> 5, lane = threadIdx.x & 31;
    int kh = warp % NKH, rg = warp / NKH;
    int k0 = kh * KT;
    const u64t* A0 = (const u64t*)aP0 + (k0 >> 1) * 64 + lane;
    const u64t* A1 = DUAL ? (const u64t*)aP1 + (k0 >> 1) * 64 + lane : (const u64t*)0;
    const float* wb0 = w0sm + rg * NRPT * padw + k0;
    const float* wb1 = DUAL ? w1sm + rg * NRPT * padw + k0 : (const float*)0;

    u64t c00 = A0[0], c01 = A0[32];
    u64t c10 = 0, c11 = 0;
    if (DUAL) { c10 = A1[0]; c11 = A1[32]; }

    #pragma unroll 4
    for (int kp = 0; kp < KT; kp += 2) {
        u64t n00 = c00, n01 = c01, n10 = c10, n11 = c11;
        if (kp + 2 < KT) {
            n00 = A0[64]; n01 = A0[96];
            if (DUAL) { n10 = A1[64]; n11 = A1[96]; }
        }
        #pragma unroll
        for (int r = 0; r < NRPT; r++) {
            u64t w2 = *(const u64t*)(wb0 + r * padw + kp);
            acc[r][0] = fma2(c00, w2, acc[r][0]);
            acc[r][1] = fma2(c01, w2, acc[r][1]);
            if (DUAL) {
                u64t v2 = *(const u64t*)(wb1 + r * padw + kp);
                acc[r][0] = fma2(c10, v2, acc[r][0]);
                acc[r][1] = fma2(c11, v2, acc[r][1]);
            }
        }
        c00 = n00; c01 = n01;
        if (DUAL) { c10 = n10; c11 = n11; }
        A0 += 64;
        if (DUAL) A1 += 64;
    }
}

template<int NROWS, int NRPT>
__device__ __forceinline__ void red_writeU(u64t (*acc)[2], float* red) {
    const int NRG = NROWS / NRPT;
    const int NKH = 16 / NRG;
    int warp = threadIdx.x >> 5, lane = threadIdx.x & 31;
    int kh = warp % NKH, rg = warp / NKH;
    #pragma unroll
    for (int r = 0; r < NRPT; r++) {
        int rr = kh * NROWS + rg * NRPT + r;
        red[rr * 66 + lane]      = hsum2(acc[r][0]);
        red[rr * 66 + lane + 32] = hsum2(acc[r][1]);
    }
}

// ctx stream of hid: A = s0[b]*ctxp0 + s1[b]*ctxp1, W cols 512..1023 of W1 rows
__device__ void mm_ctx(u64t (*acc)[2], const float* __restrict__ wsm1028, float* sm) {
    const float* sS = sm + OFF_SS;
    int warp = threadIdx.x >> 5, lane = threadIdx.x & 31;
    u64t s00 = dup2(sS[2 * lane]);
    u64t s01 = dup2(sS[2 * lane + 1]);
    u64t s10 = dup2(sS[2 * (lane + 32)]);
    u64t s11 = dup2(sS[2 * (lane + 32) + 1]);
    const u64t* c0p = (const u64t*)g_ctxpP;
    const u64t* c1p = c0p + (BH >> 1);
    int e0 = warp * 32;
    #pragma unroll 4
    for (int ep = 0; ep < 32; ep += 2) {
        int e = e0 + ep;
        int idx = (e >> 1) * 64;
        u64t x00 = c0p[idx + lane],      x01 = c1p[idx + lane];
        u64t x10 = c0p[idx + lane + 32], x11 = c1p[idx + lane + 32];
        u64t a0 = fma2(x01, s01, fma2(x00, s00, 0ull));
        u64t a1 = fma2(x11, s11, fma2(x10, s10, 0ull));
        #pragma unroll
        for (int r = 0; r < 4; r++) {
            u64t w2 = *(const u64t*)(wsm1028 + r * 1028 + 512 + e);
            acc[r][0] = fma2(a0, w2, acc[r][0]);
            acc[r][1] = fma2(a1, w2, acc[r][1]);
        }
    }
}

// ---------------- LSTM1: blocks 0..63, 32 rows (8 j) each ----------------
__device__ void lstm1_phase(int cur, int nxt, const int* __restrict__ y, int t, float* sm) {
    int tile = blockIdx.x;
    u64t acc[8][2] = {};
    mm_pipe<32, 8, 512, false>(acc, g_h1P + cur * BH, (const float*)0,
                               sm + OFF_W0, (const float*)0, 516);
    float* red = sm + OFF_RED;
    red_writeU<32, 8>(acc, red);
    __syncthreads();
    int u = threadIdx.x;
    int b = u & 63, jj = u >> 6;
    int j = tile * 8 + jj;
    float p[4] = {0.f, 0.f, 0.f, 0.f};
    #pragma unroll
    for (int kh = 0; kh < 4; kh++)
        #pragma unroll
        for (int g = 0; g < 4; g++)
            p[g] += red[(kh * 32 + g * 8 + jj) * 66 + b];
    int tok = (t == 0) ? 0 : y[b * Tc + t - 1];
    const float* e = g_emb1 + (size_t)tok * (4 * Hc);
    p[0] += e[j]; p[1] += e[Hc + j]; p[2] += e[2 * Hc + j]; p[3] += e[3 * Hc + j];
    float si = 1.f / (1.f + __expf(-p[0]));
    float sf = 1.f / (1.f + __expf(-p[1]));
    float so = 1.f / (1.f + __expf(-p[3]));
    float cN = sf * g_c1T[cur * BH + j * 64 + b] + si * tanhf(p[2]);
    float hN = so * tanhf(cN);
    g_h1P[nxt * BH + PIDX(j, b)] = hN;
    g_c1T[nxt * BH + j * 64 + b] = cN;
}

// ---------------- LSTM2: all blocks, 16 rows (4 j), dual-stream ----------------
__device__ void lstm2_phase(int cur, int nxt,
                            const float* __restrict__ bih, const float* __restrict__ bhh,
                            float* sm) {
    int tile = blockIdx.x;
    u64t acc[8][2] = {};
    mm_pipe<16, 8, 512, true>(acc, g_h2P + cur * BH, g_h1P + nxt * BH,
                              sm + OFF_WL2H, sm + OFF_WL2X, 516);
    float* red = sm + OFF_RED;
    red_writeU<16, 8>(acc, red);
    __syncthreads();
    int u = threadIdx.x;
    if (u < 256) {
        int b = u & 63, jj = u >> 6;
        int j = tile * 4 + jj;
        float p[4] = {0.f, 0.f, 0.f, 0.f};
        #pragma unroll
        for (int kh = 0; kh < 8; kh++)
            #pragma unroll
            for (int g = 0; g < 4; g++)
                p[g] += red[(kh * 16 + g * 4 + jj) * 66 + b];
        p[0] += bih[j]          + bhh[j];
        p[1] += bih[Hc + j]     + bhh[Hc + j];
        p[2] += bih[2 * Hc + j] + bhh[2 * Hc + j];
        p[3] += bih[3 * Hc + j] + bhh[3 * Hc + j];
        float si = 1.f / (1.f + __expf(-p[0]));
        float sf = 1.f / (1.f + __expf(-p[1]));
        float so = 1.f / (1.f + __expf(-p[3]));
        float cN = sf * g_c2T[cur * BH + j * 64 + b] + si * tanhf(p[2]);
        float hN = so * tanhf(cN);
        g_h2P[nxt * BH + PIDX(j, b)] = hN;
        g_c2T[nxt * BH + j * 64 + b] = cN;
    }
}

// ---------------- attention: split-KV, 2 blocks per batch ----------------
struct AttnS {
    float qh[512];
    float scl[256];
    float ctxp[3 * 512];
    float red[16];
    float red2[16];
};

__device__ __forceinline__ float dot8h(const float* qr, uint4 pk) {
    const __half2* p2 = (const __half2*)&pk;
    float s = 0.f;
    #pragma unroll
    for (int q = 0; q < 4; q++) {
        float2 f = __half22float2(p2[q]);
        s += qr[q * 2] * f.x + qr[q * 2 + 1] * f.y;
    }
    return s;
}

__device__ void attn_phase(int nxt, float* __restrict__ attn_half, float* sm) {
    int pairb = blockIdx.x >> 1, half = blockIdx.x & 1;
    AttnS* at = (AttnS*)(sm + OFF_AB);
    int tid = threadIdx.x, warp = tid >> 5, lane = tid & 31;
    int s0 = half * 256;

    at->qh[tid] = g_h2P[nxt * BH + PIDX(tid, pairb)];
    __syncthreads();

    float hr[16];
    #pragma unroll
    for (int q = 0; q < 4; q++) {
        float4 f = *(const float4*)&at->qh[lane * 16 + q * 4];
        hr[q * 4 + 0] = f.x; hr[q * 4 + 1] = f.y;
        hr[q * 4 + 2] = f.z; hr[q * 4 + 3] = f.w;
    }

    // scores: sc = (h2 . KK[b,s] + c0[b,s]) * scale
    #pragma unroll
    for (int i = 0; i < 8; i++) {
        int sA = s0 + warp + i * 32, sB = sA + 16;
        const __half* ka = g_kk + ((size_t)(pairb * Sc + sA)) * Ec + lane * 16;
        const __half* kb = g_kk + ((size_t)(pairb * Sc + sB)) * Ec + lane * 16;
        float sa = dot8h(hr, *(const uint4*)ka) + dot8h(hr + 8, *(const uint4*)(ka + 8));
        float sb = dot8h(hr, *(const uint4*)kb) + dot8h(hr + 8, *(const uint4*)(kb + 8));
        #pragma unroll
        for (int o = 16; o; o >>= 1) {
            sa += __shfl_down_sync(~0u, sa, o);
            sb += __shfl_down_sync(~0u, sb, o);
        }
        if (lane == 0) {
            at->scl[sA - s0] = (sa + g_c0[pairb * Sc + sA]) * 0.0625f;
            at->scl[sB - s0] = (sb + g_c0[pairb * Sc + sB]) * 0.0625f;
        }
    }
    __syncthreads();

    // local softmax partials over 256
    float v = (tid < 256) ? at->scl[tid] : -3.0e38f;
    float m = v;
    #pragma unroll
    for (int o = 16; o; o >>= 1) m = fmaxf(m, __shfl_xor_sync(~0u, m, o));
    if (lane == 0) at->red[warp] = m;
    __syncthreads();
    float mm = at->red[0];
    #pragma unroll
    for (int w = 1; w < 8; w++) mm = fmaxf(mm, at->red[w]);
    float e = (tid < 256) ? __expf(v - mm) : 0.f;
    float ssum = e;
    #pragma unroll
    for (int o = 16; o; o >>= 1) ssum += __shfl_xor_sync(~0u, ssum, o);
    if (lane == 0) at->red2[warp] = ssum;
    __syncthreads();
    if (tid == 0) {
        float Z = 0.f;
        #pragma unroll
        for (int w = 0; w < 16; w++) Z += at->red2[w];
        g_mz[pairb * 2 + half] = make_float2(mm, Z);
    }
    if (tid < 256) {
        at->scl[tid] = e;
        attn_half[tid] = e;              // unnormalized; rescaled in PD
    }
    __syncthreads();

    // partial ctx over this half (fp16 V), 4-way s-split
    int sq = tid >> 7;
    int e4 = (tid & 127) * 4;
    const __half* vb = g_vh + (size_t)pairb * Sc * Ec + e4;
    float a0 = 0.f, a1 = 0.f, a2 = 0.f, a3 = 0.f;
    int sb2 = sq * 64;
    #pragma unroll 8
    for (int i2 = 0; i2 < 64; i2++) {
        float pp = at->scl[sb2 + i2];
        uint2 pk = *(const uint2*)(vb + (size_t)(s0 + sb2 + i2) * Ec);
        float2 f0 = __half22float2(*(__half2*)&pk.x);
        float2 f1 = __half22float2(*(__half2*)&pk.y);
        a0 += pp * f0.x; a1 += pp * f0.y; a2 += pp * f1.x; a3 += pp * f1.y;
    }
    if (sq) {
        float* cp = at->ctxp + (sq - 1) * 512 + e4;
        cp[0] = a0; cp[1] = a1; cp[2] = a2; cp[3] = a3;
    }
    __syncthreads();
    if (sq == 0) {
        #pragma unroll
        for (int q = 0; q < 3; q++) {
            const float* cp = at->ctxp + q * 512 + e4;
            a0 += cp[0]; a1 += cp[1]; a2 += cp[2]; a3 += cp[3];
        }
        u64t* gp = (u64t*)(g_ctxpP + (size_t)half * BH);
        gp[(e4 >> 1) * 64 + pairb]       = pack2(a0, a1);
        gp[((e4 + 2) >> 1) * 64 + pairb] = pack2(a2, a3);
    }
}

// ---------------- hid: merge scales + rescale attn + hid GEMM ----------------
__device__ void hid_phase(int nxt, const float* __restrict__ b1,
                          float* __restrict__ attn_half, float* sm) {
    float* sS = sm + OFF_SS;
    int tid = threadIdx.x;
    if (tid < 128) {
        int bb = tid >> 1, h = tid & 1;
        float2 mz0 = g_mz[bb * 2 + 0];
        float2 mz1 = g_mz[bb * 2 + 1];
        float m = fmaxf(mz0.x, mz1.x);
        float Z = mz0.y * __expf(mz0.x - m) + mz1.y * __expf(mz1.x - m);
        float mh = h ? mz1.x : mz0.x;
        sS[tid] = __expf(mh - m) / Z;
    }
    __syncthreads();
    {
        float f = sS[blockIdx.x];
        if (tid < 256) attn_half[tid] *= f;
    }
    u64t acc[4][2] = {};
    mm_pipe<4, 4, 512, false>(acc, g_h2P + nxt * BH, (const float*)0,
                              sm + OFF_WHID, (const float*)0, 1028);
    mm_ctx(acc, sm + OFF_WHID, sm);
    float* red = sm + OFF_RED;
    red_writeU<4, 4>(acc, red);
    __syncthreads();
    int u = threadIdx.x;
    if (u < 256) {
        int b = u & 63, r = u >> 6;
        int j = blockIdx.x * 4 + r;
        float sum = b1[j];
        #pragma unroll
        for (int kh = 0; kh < 16; kh++) sum += red[(kh * 4 + r) * 66 + b];
        g_hidP[PIDX(j, b)] = fmaxf(sum, 0.f);
    }
}

// ---------------- logits: B-blocks, 16 rows each ----------------
__device__ void logits_phase(const float* __restrict__ bcls, float* __restrict__ outL,
                             int t, float* sm) {
    int tile = blockIdx.x - 64;
    u64t acc[8][2] = {};
    mm_pipe<16, 8, 512, false>(acc, g_hidP, (const float*)0,
                               sm + OFF_W0, (const float*)0, 516);
    float* red = sm + OFF_RED;
    red_writeU<16, 8>(acc, red);
    __syncthreads();
    int u = threadIdx.x;
    int r = u & 15, b0 = (u >> 4) * 2;
    int j = tile * 16 + r;
    if (j < Vc) {
        float s0 = bcls[j], s1 = bcls[j];
        #pragma unroll
        for (int kh = 0; kh < 8; kh++) {
            s0 += red[(kh * 16 + r) * 66 + b0];
            s1 += red[(kh * 16 + r) * 66 + b0 + 1];
        }
        outL[((size_t)b0 * Tc + t) * Vc + j]       = s0;
        outL[((size_t)(b0 + 1) * Tc + t) * Vc + j] = s1;
    }
}

// ---------------- weight preload ----------------
__device__ void preload_weights(float* sm, const float* __restrict__ Whh1,
                                const float* __restrict__ Whh2, const float* __restrict__ Wih2,
                                const float* __restrict__ W1, const float* __restrict__ Wemb) {
    int tid = threadIdx.x;
    int tile = blockIdx.x;
    if (tile < 64) {
        for (int i = tid; i < 32 * 128; i += NTHR) {
            int r = i >> 7, c4 = (i & 127) * 4;
            int srow = (r >> 3) * Hc + tile * 8 + (r & 7);
            *(float4*)&sm[OFF_W0 + r * 516 + c4] = *(const float4*)&Whh1[(size_t)srow * Hc + c4];
        }
    } else {
        int tl = tile - 64;
        for (int i = tid; i < 16 * 128; i += NTHR) {
            int r = i >> 7, c4 = (i & 127) * 4;
            int srow = tl * 16 + r; if (srow >= Vc) srow = Vc - 1;
            *(float4*)&sm[OFF_W0 + r * 516 + c4] = *(const float4*)&Wemb[(size_t)srow * Hc + c4];
        }
    }
    for (int i = tid; i < 16 * 128; i += NTHR) {
        int r = i >> 7, c4 = (i & 127) * 4;
        int srow = (r >> 2) * Hc + tile * 4 + (r & 3);
        *(float4*)&sm[OFF_WL2H + r * 516 + c4] = *(const float4*)&Whh2[(size_t)srow * Hc + c4];
        *(float4*)&sm[OFF_WL2X + r * 516 + c4] = *(const float4*)&Wih2[(size_t)srow * Hc + c4];
    }
    for (int i = tid; i < 4 * 256; i += NTHR) {
        int r = i >> 8, c4 = (i & 255) * 4;
        *(float4*)&sm[OFF_WHID + r * 1028 + c4] =
            *(const float4*)&W1[(size_t)(tile * 4 + r) * (Hc + Ec) + c4];
    }
}

// ---------------- precompute 64x64 GEMM tile (f32x2, k-paired staging) ----------------
__device__ __forceinline__ void storeC(float* C, size_t idx, float v) { C[idx] = v; }
__device__ __forceinline__ void storeC(__half* C, size_t idx, float v) { C[idx] = __float2half(v); }

template<bool WT, class OUT>
__device__ void gemm_tile2(const float* __restrict__ A, const float* __restrict__ W,
                           const float* __restrict__ b1v, const float* __restrict__ b2v,
                           OUT* __restrict__ C, int M, int N, int K, int m0, int n0, float* sm) {
    u64t* As2 = (u64t*)(sm + OFF_AB);          // [64][9] u64 (k-pairs)
    u64t* Ws2 = As2 + 64 * 9;                  // [64][9] u64
    int tid = threadIdx.x;
    int tx = tid & 15, ty = tid >> 4;          // ty in [0,32): row-pair
    u64t acc[2][4] = {};
    for (int kb = 0; kb < K; kb += 16) {
        __syncthreads();
        {
            int r = tid >> 3, kkp = tid & 7;   // 64 rows x 8 k-pairs
            int ra = m0 + r; if (ra >= M) ra = M - 1;
            float2 av = *(const float2*)&A[(size_t)ra * K + kb + kkp * 2];
            As2[r * 9 + kkp] = pack2(av.x, av.y);
            if (!WT) {
                float2 wv = *(const float2*)&W[(size_t)(n0 + r) * K + kb + kkp * 2];
                Ws2[r * 9 + kkp] = pack2(wv.x, wv.y);
            } else {
                float w0 = W[(size_t)(kb + kkp * 2) * N + n0 + r];
                float w1 = W[(size_t)(kb + kkp * 2 + 1) * N + n0 + r];
                Ws2[r * 9 + kkp] = pack2(w0, w1);
            }
        }
        __syncthreads();
        #pragma unroll
        for (int kkp = 0; kkp < 8; kkp++) {
            u64t a0 = As2[(ty * 2) * 9 + kkp];
            u64t a1 = As2[(ty * 2 + 1) * 9 + kkp];
            #pragma unroll
            for (int jv = 0; jv < 4; jv++) {
                u64t w2 = Ws2[(tx * 4 + jv) * 9 + kkp];
                acc[0][jv] = fma2(a0, w2, acc[0][jv]);
                acc[1][jv] = fma2(a1, w2, acc[1][jv]);
            }
        }
    }
    __syncthreads();
    #pragma unroll
    for (int i = 0; i < 2; i++) {
        int row = m0 + ty * 2 + i;
        if (row < M) {
            #pragma unroll
            for (int jv = 0; jv < 4; jv++) {
                int col = n0 + tx * 4 + jv;
                float vv = hsum2(acc[i][jv]);
                if (b1v) vv += b1v[col];
                if (b2v) vv += b2v[col];
                storeC(C, (size_t)row * N + col, vv);
            }
        }
    }
}

// ---------------- persistent kernel ----------------
__global__ void __launch_bounds__(NTHR, 1)
decoder_kernel(const float* __restrict__ enc, const int* __restrict__ y,
               const float* __restrict__ Wemb,
               const float* __restrict__ Wih1, const float* __restrict__ bih1,
               const float* __restrict__ Whh1, const float* __restrict__ bhh1,
               const float* __restrict__ Wih2, const float* __restrict__ bih2,
               const float* __restrict__ Whh2, const float* __restrict__ bhh2,
               const float* __restrict__ Wq,  const float* __restrict__ bq,
               const float* __restrict__ Wk,  const float* __restrict__ bk,
               const float* __restrict__ Wv,  const float* __restrict__ bv,
               const float* __restrict__ W1,  const float* __restrict__ b1,
               const float* __restrict__ bcls,
               float* __restrict__ outL, float* __restrict__ attnB,
               int attnBS, int attnTS)
{
    extern __shared__ float sm[];
    int tid = threadIdx.x;
    unsigned gen = g_flags[blockIdx.x * 32];   // replay-safe base

    for (int i = blockIdx.x * NTHR + tid; i < BH; i += NBLK * NTHR) {
        g_h1P[i] = 0.f; g_c1T[i] = 0.f; g_h2P[i] = 0.f; g_c2T[i] = 0.f;
    }
    preload_weights(sm, Whh1, Whh2, Wih2, W1, Wemb);
    gsync(++gen);

    // pre1: K fp32 (temp), V fp16, LSTM1 token table
    {
        const int nKt = (Bc * Sc / 64) * (KQc / 64);
        const int nVt = (Bc * Sc / 64) * (Ec / 64);
        const int nEt = 16 * (4 * Hc / 64);
        for (int idx = blockIdx.x; idx < nKt + nVt + nEt; idx += NBLK) {
            if (idx < nKt) {
                int m0 = (idx / (KQc / 64)) * 64, n0 = (idx % (KQc / 64)) * 64;
                gemm_tile2<false>(enc, Wk, bk, (const float*)0, g_ktmp,
                                  Bc * Sc, KQc, Ec, m0, n0, sm);
            } else if (idx < nKt + nVt) {
                int i2 = idx - nKt;
                int m0 = (i2 / (Ec / 64)) * 64, n0 = (i2 % (Ec / 64)) * 64;
                gemm_tile2<false>(enc, Wv, bv, (const float*)0, g_vh,
                                  Bc * Sc, Ec, Ec, m0, n0, sm);
            } else {
                int i2 = idx - nKt - nVt;
                int m0 = (i2 / 32) * 64, n0 = (i2 % 32) * 64;
                gemm_tile2<false>(Wemb, Wih1, bih1, bhh1, g_emb1,
                                  Vc, 4 * Hc, Hc, m0, n0, sm);
            }
        }
    }
    gsync(++gen);

    // pre2: KK = K @ Wq (fp16) and c0 = K . bq
    {
        const int nT = (Bc * Sc / 64) * (Ec / 64);
        for (int idx = blockIdx.x; idx < nT; idx += NBLK) {
            int m0 = (idx / (Ec / 64)) * 64, n0 = (idx % (Ec / 64)) * 64;
            gemm_tile2<true>(g_ktmp, Wq, (const float*)0, (const float*)0, g_kk,
                             Bc * Sc, Ec, KQc, m0, n0, sm);
        }
        int lane = tid & 31;
        int gw = (blockIdx.x * NTHR + tid) >> 5;
        float bqr[8];
        #pragma unroll
        for (int q = 0; q < 8; q++) bqr[q] = bq[lane * 8 + q];
        for (int m = gw; m < Bc * Sc; m += (NBLK * NTHR) >> 5) {
            const float* kr = g_ktmp + (size_t)m * KQc + lane * 8;
            float4 k0 = *(const float4*)kr;
            float4 k1 = *(const float4*)(kr + 4);
            float s = bqr[0]*k0.x + bqr[1]*k0.y + bqr[2]*k0.z + bqr[3]*k0.w
                    + bqr[4]*k1.x + bqr[5]*k1.y + bqr[6]*k1.z + bqr[7]*k1.w;
            #pragma unroll
            for (int o = 16; o; o >>= 1) s += __shfl_down_sync(~0u, s, o);
            if (lane == 0) g_c0[m] = s;
        }
    }
    gsync(++gen);

    int pairb = blockIdx.x >> 1, half = blockIdx.x & 1;

    for (int t = 0; t < Tc; t++) {
        int cur = t & 1, nxt = cur ^ 1;

        // PA: LSTM1 (blocks 0..63) || logits(t-1) (blocks 64..127)
        if (blockIdx.x < 64)
            lstm1_phase(cur, nxt, y, t, sm);
        else if (t > 0)
            logits_phase(bcls, outL, t - 1, sm);
        gsync(++gen);

        // PB: LSTM2 (all blocks, dual-stream)
        lstm2_phase(cur, nxt, bih2, bhh2, sm);
        gsync(++gen);

        // PC: split-KV attention (all blocks; 2 per batch)
        {
            float* ah = attnB + (size_t)pairb * attnBS + (size_t)t * attnTS + half * 256;
            attn_phase(nxt, ah, sm);
        }
        gsync(++gen);

        // PD: merge + rescale attn + hid
        {
            float* ah = attnB + (size_t)pairb * attnBS + (size_t)t * attnTS + half * 256;
            hid_phase(nxt, b1, ah, sm);
        }
        gsync(++gen);
    }

    // final logits for t = Tc-1
    if (blockIdx.x >= 64)
        logits_phase(bcls, outL, Tc - 1, sm);
}

// ---------------- launch ----------------
extern "C" void kernel_launch(void* const* d_in, const int* in_sizes, int n_in,
                              void* d_out, int out_size) {
    const float* enc   = (const float*)d_in[0];
    const int*   y     = (const int*)  d_in[1];
    const float* Wemb  = (const float*)d_in[2];
    const float* Wih1  = (const float*)d_in[3];
    const float* bih1  = (const float*)d_in[4];
    const float* Whh1  = (const float*)d_in[5];
    const float* bhh1  = (const float*)d_in[6];
    const float* Wih2  = (const float*)d_in[7];
    const float* bih2  = (const float*)d_in[8];
    const float* Whh2  = (const float*)d_in[9];
    const float* bhh2  = (const float*)d_in[10];
    const float* Wq    = (const float*)d_in[11];
    const float* bq    = (const float*)d_in[12];
    const float* Wk    = (const float*)d_in[13];
    const float* bk    = (const float*)d_in[14];
    const float* Wv    = (const float*)d_in[15];
    const float* bv    = (const float*)d_in[16];
    const float* W1    = (const float*)d_in[17];
    const float* b1    = (const float*)d_in[18];
    const float* bcls  = (const float*)d_in[19];

    float* outL = (float*)d_out;
    long long need = (long long)Bc * Tc * Vc + (long long)Bc * Tc * Sc;

    float* attnB; int attnBS, attnTS;
    if ((long long)out_size >= need) {
        attnB = outL + (size_t)Bc * Tc * Vc;
        attnBS = Tc * Sc; attnTS = Sc;
    } else {
        cudaGetSymbolAddress((void**)&attnB, g_attn_dummy);
        attnBS = Sc; attnTS = 0;
    }

    cudaFuncSetAttribute(decoder_kernel,
                         cudaFuncAttributeMaxDynamicSharedMemorySize, SMEM_BYTES);

    decoder_kernel<<<NBLK, NTHR, SMEM_BYTES>>>(enc, y, Wemb, Wih1, bih1, Whh1, bhh1,
                                               Wih2, bih2, Whh2, bhh2, Wq, bq, Wk, bk,
                                               Wv, bv, W1, b1, bcls, outL,
                                               attnB, attnBS, attnTS);
}

// round 15
// speedup vs baseline: 1.0830x; 1.0830x over previous
#include <cuda_runtime.h>
#include <cuda_fp16.h>
#include <math.h>

#define Bc  64
#define Sc  512
#define Tc  256
#define Ec  512
#define Hc  512
#define KQc 256
#define Vc  1000
#define BH  (Bc*Hc)
#define NBLK 128
#define NTHR 512

typedef unsigned long long u64t;

// k-paired transposed activation index: aP[(j>>1)*128 + b*2 + (j&1)]
#define PIDX(j,b) ((((j)>>1)<<7) + ((b)<<1) + ((j)&1))

// ---------------- dynamic smem layout (float offsets) ----------------
#define OFF_W0    0                      // A-blocks: Whh1 32x516 ; B-blocks: Wemb 16x516
#define OFF_WL2H  16512                  // Whh2 16x516
#define OFF_WL2X  24768                  // Wih2 16x516
#define OFF_WHID  33024                  // W1 4x1028 (full K=1024)
#define OFF_AB    37136                  // attn struct + precompute tiles
#define OFF_RED   45840                  // reduction 128x66
#define OFF_SS    (OFF_RED + 8320)       // 128 merge scales
#define SMEM_F    54288
#define SMEM_BYTES (SMEM_F * 4)          // 217152 B

// ---------------- device scratch ----------------
__device__ float  g_ktmp[(size_t)Bc*Sc*KQc];   // K fp32 (precompute temp)
__device__ __half g_kk[(size_t)Bc*Sc*Ec];      // KK = K @ Wq  [B*S, 512] fp16
__device__ float  g_c0[(size_t)Bc*Sc];         // bq . k
__device__ __half g_vh[(size_t)Bc*Sc*Ec];      // V cache fp16
__device__ float  g_emb1[(size_t)Vc*4*Hc];     // token -> LSTM1 x-side gate preacts
__device__ __align__(16) float g_h1P[2*BH];    // h1 transposed k-paired, double-buffered
__device__ __align__(16) float g_h2P[2*BH];
__device__ __align__(16) float g_c1T[2*BH];    // c transposed [j][b]
__device__ __align__(16) float g_c2T[2*BH];
__device__ __align__(16) float g_hidP[BH];     // hid transposed k-paired
__device__ __align__(16) float g_ctxpP[2*(size_t)Bc*Ec];  // ctx partials k-paired [half]
__device__ float2 g_mz[2*Bc];                  // per (b,half): {m_local, Z_local}
__device__ float  g_attn_dummy[Bc*Sc];

// ---------------- grid barrier: all-poll (replay-safe) ----------------
__device__ volatile unsigned g_flags[NBLK*32];

__device__ __forceinline__ void gsync(unsigned gen) {
    __syncthreads();
    if (threadIdx.x == 0) {
        __threadfence();
        g_flags[blockIdx.x * 32] = gen;
    }
    if (threadIdx.x < NBLK) {
        while (g_flags[threadIdx.x * 32] < gen) { }
        __threadfence();
    }
    __syncthreads();
}

// ---------------- f32x2 packed FMA ----------------
__device__ __forceinline__ u64t fma2(u64t a, u64t b, u64t c) {
    u64t d;
    asm("fma.rn.f32x2 %0, %1, %2, %3;" : "=l"(d) : "l"(a), "l"(b), "l"(c));
    return d;
}
__device__ __forceinline__ float hsum2(u64t v) {
    return __uint_as_float((unsigned)v) + __uint_as_float((unsigned)(v >> 32));
}
__device__ __forceinline__ u64t pack2(float lo, float hi) {
    u64t d;
    asm("mov.b64 %0, {%1, %2};" : "=l"(d) : "r"(__float_as_uint(lo)), "r"(__float_as_uint(hi)));
    return d;
}
__device__ __forceinline__ u64t dup2(float x) { return pack2(x, x); }

// ---------------- unstaged GEMM core ----------------
// warp = (rg, kh): kh = warp % NKH, rg = warp / NKH; NKH = 16/(NROWS/NRPT).
// Thread covers W rows rg*NRPT..+NRPT-1 (BROADCAST loads), batches (lane, lane+32),
// k in [kh*KT, (kh+1)*KT). A read directly from L2 (k-paired transposed).
// unroll 8: ~16 independent LDG.64 hoistable per strand -> covers L2 latency.
template<int NROWS, int NRPT, int KTOT>
__device__ __forceinline__ void mm_unstaged(u64t (*acc)[2], const float* __restrict__ aP,
                                            const float* __restrict__ wsm, int padw) {
    const int NRG = NROWS / NRPT;
    const int NKH = 16 / NRG;
    const int KT = KTOT / NKH;
    int warp = threadIdx.x >> 5, lane = threadIdx.x & 31;
    int kh = warp % NKH, rg = warp / NKH;
    const float* wb = wsm + rg * NRPT * padw;
    const u64t* a64 = (const u64t*)aP;
    int k0 = kh * KT;
    #pragma unroll 8
    for (int kp = 0; kp < KT; kp += 2) {
        int k = k0 + kp;
        u64t a0 = a64[(k >> 1) * 64 + lane];
        u64t a1 = a64[(k >> 1) * 64 + lane + 32];
        #pragma unroll
        for (int r = 0; r < NRPT; r++) {
            u64t w2 = *(const u64t*)(wb + r * padw + k);
            acc[r][0] = fma2(a0, w2, acc[r][0]);
            acc[r][1] = fma2(a1, w2, acc[r][1]);
        }
    }
}

template<int NROWS, int NRPT>
__device__ __forceinline__ void red_writeU(u64t (*acc)[2], float* red) {
    const int NRG = NROWS / NRPT;
    const int NKH = 16 / NRG;
    int warp = threadIdx.x >> 5, lane = threadIdx.x & 31;
    int kh = warp % NKH, rg = warp / NKH;
    #pragma unroll
    for (int r = 0; r < NRPT; r++) {
        int rr = kh * NROWS + rg * NRPT + r;
        red[rr * 66 + lane]      = hsum2(acc[r][0]);
        red[rr * 66 + lane + 32] = hsum2(acc[r][1]);
    }
}

// ctx stream of hid: A = s0[b]*ctxp0 + s1[b]*ctxp1, W cols 512..1023 of W1 rows
__device__ void mm_ctx(u64t (*acc)[2], const float* __restrict__ wsm1028, float* sm) {
    const float* sS = sm + OFF_SS;
    int warp = threadIdx.x >> 5, lane = threadIdx.x & 31;
    u64t s00 = dup2(sS[2 * lane]);
    u64t s01 = dup2(sS[2 * lane + 1]);
    u64t s10 = dup2(sS[2 * (lane + 32)]);
    u64t s11 = dup2(sS[2 * (lane + 32) + 1]);
    const u64t* c0p = (const u64t*)g_ctxpP;
    const u64t* c1p = c0p + (BH >> 1);
    int e0 = warp * 32;
    #pragma unroll 4
    for (int ep = 0; ep < 32; ep += 2) {
        int e = e0 + ep;
        int idx = (e >> 1) * 64;
        u64t x00 = c0p[idx + lane],      x01 = c1p[idx + lane];
        u64t x10 = c0p[idx + lane + 32], x11 = c1p[idx + lane + 32];
        u64t a0 = fma2(x01, s01, fma2(x00, s00, 0ull));
        u64t a1 = fma2(x11, s11, fma2(x10, s10, 0ull));
        #pragma unroll
        for (int r = 0; r < 4; r++) {
            u64t w2 = *(const u64t*)(wsm1028 + r * 1028 + 512 + e);
            acc[r][0] = fma2(a0, w2, acc[r][0]);
            acc[r][1] = fma2(a1, w2, acc[r][1]);
        }
    }
}

// ---------------- LSTM1: blocks 0..63, 32 rows (8 j) each ----------------
__device__ void lstm1_phase(int cur, int nxt, const int* __restrict__ y, int t, float* sm) {
    int tile = blockIdx.x;
    u64t acc[8][2] = {};
    mm_unstaged<32, 8, 512>(acc, g_h1P + cur * BH, sm + OFF_W0, 516);
    float* red = sm + OFF_RED;
    red_writeU<32, 8>(acc, red);
    __syncthreads();
    int u = threadIdx.x;
    int b = u & 63, jj = u >> 6;
    int j = tile * 8 + jj;
    float p[4] = {0.f, 0.f, 0.f, 0.f};
    #pragma unroll
    for (int kh = 0; kh < 4; kh++)
        #pragma unroll
        for (int g = 0; g < 4; g++)
            p[g] += red[(kh * 32 + g * 8 + jj) * 66 + b];
    int tok = (t == 0) ? 0 : y[b * Tc + t - 1];
    const float* e = g_emb1 + (size_t)tok * (4 * Hc);
    p[0] += e[j]; p[1] += e[Hc + j]; p[2] += e[2 * Hc + j]; p[3] += e[3 * Hc + j];
    float si = 1.f / (1.f + __expf(-p[0]));
    float sf = 1.f / (1.f + __expf(-p[1]));
    float so = 1.f / (1.f + __expf(-p[3]));
    float cN = sf * g_c1T[cur * BH + j * 64 + b] + si * tanhf(p[2]);
    float hN = so * tanhf(cN);
    g_h1P[nxt * BH + PIDX(j, b)] = hN;
    g_c1T[nxt * BH + j * 64 + b] = cN;
}

// ---------------- LSTM2: all blocks, 16 rows (4 j) ----------------
__device__ void lstm2_phase(int cur, int nxt,
                            const float* __restrict__ bih, const float* __restrict__ bhh,
                            float* sm) {
    int tile = blockIdx.x;
    u64t acc[8][2] = {};
    mm_unstaged<16, 8, 512>(acc, g_h2P + cur * BH, sm + OFF_WL2H, 516);
    mm_unstaged<16, 8, 512>(acc, g_h1P + nxt * BH, sm + OFF_WL2X, 516);
    float* red = sm + OFF_RED;
    red_writeU<16, 8>(acc, red);
    __syncthreads();
    int u = threadIdx.x;
    if (u < 256) {
        int b = u & 63, jj = u >> 6;
        int j = tile * 4 + jj;
        float p[4] = {0.f, 0.f, 0.f, 0.f};
        #pragma unroll
        for (int kh = 0; kh < 8; kh++)
            #pragma unroll
            for (int g = 0; g < 4; g++)
                p[g] += red[(kh * 16 + g * 4 + jj) * 66 + b];
        p[0] += bih[j]          + bhh[j];
        p[1] += bih[Hc + j]     + bhh[Hc + j];
        p[2] += bih[2 * Hc + j] + bhh[2 * Hc + j];
        p[3] += bih[3 * Hc + j] + bhh[3 * Hc + j];
        float si = 1.f / (1.f + __expf(-p[0]));
        float sf = 1.f / (1.f + __expf(-p[1]));
        float so = 1.f / (1.f + __expf(-p[3]));
        float cN = sf * g_c2T[cur * BH + j * 64 + b] + si * tanhf(p[2]);
        float hN = so * tanhf(cN);
        g_h2P[nxt * BH + PIDX(j, b)] = hN;
        g_c2T[nxt * BH + j * 64 + b] = cN;
    }
}

// ---------------- attention: split-KV, 2 blocks per batch ----------------
struct AttnS {
    float qh[512];
    float scl[256];
    float ctxp[3 * 512];
    float red[16];
    float red2[16];
};

__device__ __forceinline__ float dot8h(const float* qr, uint4 pk) {
    const __half2* p2 = (const __half2*)&pk;
    float s = 0.f;
    #pragma unroll
    for (int q = 0; q < 4; q++) {
        float2 f = __half22float2(p2[q]);
        s += qr[q * 2] * f.x + qr[q * 2 + 1] * f.y;
    }
    return s;
}

__device__ void attn_phase(int nxt, float* __restrict__ attn_half, float* sm) {
    int pairb = blockIdx.x >> 1, half = blockIdx.x & 1;
    AttnS* at = (AttnS*)(sm + OFF_AB);
    int tid = threadIdx.x, warp = tid >> 5, lane = tid & 31;
    int s0 = half * 256;

    at->qh[tid] = g_h2P[nxt * BH + PIDX(tid, pairb)];
    __syncthreads();

    float hr[16];
    #pragma unroll
    for (int q = 0; q < 4; q++) {
        float4 f = *(const float4*)&at->qh[lane * 16 + q * 4];
        hr[q * 4 + 0] = f.x; hr[q * 4 + 1] = f.y;
        hr[q * 4 + 2] = f.z; hr[q * 4 + 3] = f.w;
    }

    // scores: sc = (h2 . KK[b,s] + c0[b,s]) * scale
    #pragma unroll
    for (int i = 0; i < 8; i++) {
        int sA = s0 + warp + i * 32, sB = sA + 16;
        const __half* ka = g_kk + ((size_t)(pairb * Sc + sA)) * Ec + lane * 16;
        const __half* kb = g_kk + ((size_t)(pairb * Sc + sB)) * Ec + lane * 16;
        float sa = dot8h(hr, *(const uint4*)ka) + dot8h(hr + 8, *(const uint4*)(ka + 8));
        float sb = dot8h(hr, *(const uint4*)kb) + dot8h(hr + 8, *(const uint4*)(kb + 8));
        #pragma unroll
        for (int o = 16; o; o >>= 1) {
            sa += __shfl_down_sync(~0u, sa, o);
            sb += __shfl_down_sync(~0u, sb, o);
        }
        if (lane == 0) {
            at->scl[sA - s0] = (sa + g_c0[pairb * Sc + sA]) * 0.0625f;
            at->scl[sB - s0] = (sb + g_c0[pairb * Sc + sB]) * 0.0625f;
        }
    }
    __syncthreads();

    // local softmax partials over 256
    float v = (tid < 256) ? at->scl[tid] : -3.0e38f;
    float m = v;
    #pragma unroll
    for (int o = 16; o; o >>= 1) m = fmaxf(m, __shfl_xor_sync(~0u, m, o));
    if (lane == 0) at->red[warp] = m;
    __syncthreads();
    float mm = at->red[0];
    #pragma unroll
    for (int w = 1; w < 8; w++) mm = fmaxf(mm, at->red[w]);
    float e = (tid < 256) ? __expf(v - mm) : 0.f;
    float ssum = e;
    #pragma unroll
    for (int o = 16; o; o >>= 1) ssum += __shfl_xor_sync(~0u, ssum, o);
    if (lane == 0) at->red2[warp] = ssum;
    __syncthreads();
    if (tid == 0) {
        float Z = 0.f;
        #pragma unroll
        for (int w = 0; w < 16; w++) Z += at->red2[w];
        g_mz[pairb * 2 + half] = make_float2(mm, Z);
    }
    if (tid < 256) {
        at->scl[tid] = e;
        attn_half[tid] = e;              // unnormalized; rescaled in PD
    }
    __syncthreads();

    // partial ctx over this half (fp16 V), 4-way s-split
    int sq = tid >> 7;
    int e4 = (tid & 127) * 4;
    const __half* vb = g_vh + (size_t)pairb * Sc * Ec + e4;
    float a0 = 0.f, a1 = 0.f, a2 = 0.f, a3 = 0.f;
    int sb2 = sq * 64;
    #pragma unroll 8
    for (int i2 = 0; i2 < 64; i2++) {
        float pp = at->scl[sb2 + i2];
        uint2 pk = *(const uint2*)(vb + (size_t)(s0 + sb2 + i2) * Ec);
        float2 f0 = __half22float2(*(__half2*)&pk.x);
        float2 f1 = __half22float2(*(__half2*)&pk.y);
        a0 += pp * f0.x; a1 += pp * f0.y; a2 += pp * f1.x; a3 += pp * f1.y;
    }
    if (sq) {
        float* cp = at->ctxp + (sq - 1) * 512 + e4;
        cp[0] = a0; cp[1] = a1; cp[2] = a2; cp[3] = a3;
    }
    __syncthreads();
    if (sq == 0) {
        #pragma unroll
        for (int q = 0; q < 3; q++) {
            const float* cp = at->ctxp + q * 512 + e4;
            a0 += cp[0]; a1 += cp[1]; a2 += cp[2]; a3 += cp[3];
        }
        u64t* gp = (u64t*)(g_ctxpP + (size_t)half * BH);
        gp[(e4 >> 1) * 64 + pairb]       = pack2(a0, a1);
        gp[((e4 + 2) >> 1) * 64 + pairb] = pack2(a2, a3);
    }
}

// ---------------- hid: merge scales + rescale attn + hid GEMM ----------------
__device__ void hid_phase(int nxt, const float* __restrict__ b1,
                          float* __restrict__ attn_half, float* sm) {
    float* sS = sm + OFF_SS;
    int tid = threadIdx.x;
    if (tid < 128) {
        int bb = tid >> 1, h = tid & 1;
        float2 mz0 = g_mz[bb * 2 + 0];
        float2 mz1 = g_mz[bb * 2 + 1];
        float m = fmaxf(mz0.x, mz1.x);
        float Z = mz0.y * __expf(mz0.x - m) + mz1.y * __expf(mz1.x - m);
        float mh = h ? mz1.x : mz0.x;
        sS[tid] = __expf(mh - m) / Z;
    }
    __syncthreads();
    {
        float f = sS[blockIdx.x];
        if (tid < 256) attn_half[tid] *= f;
    }
    u64t acc[4][2] = {};
    mm_unstaged<4, 4, 512>(acc, g_h2P + nxt * BH, sm + OFF_WHID, 1028);
    mm_ctx(acc, sm + OFF_WHID, sm);
    float* red = sm + OFF_RED;
    red_writeU<4, 4>(acc, red);
    __syncthreads();
    int u = threadIdx.x;
    if (u < 256) {
        int b = u & 63, r = u >> 6;
        int j = blockIdx.x * 4 + r;
        float sum = b1[j];
        #pragma unroll
        for (int kh = 0; kh < 16; kh++) sum += red[(kh * 4 + r) * 66 + b];
        g_hidP[PIDX(j, b)] = fmaxf(sum, 0.f);
    }
}

// ---------------- logits: B-blocks, 16 rows each ----------------
__device__ void logits_phase(const float* __restrict__ bcls, float* __restrict__ outL,
                             int t, float* sm) {
    int tile = blockIdx.x - 64;
    u64t acc[8][2] = {};
    mm_unstaged<16, 8, 512>(acc, g_hidP, sm + OFF_W0, 516);
    float* red = sm + OFF_RED;
    red_writeU<16, 8>(acc, red);
    __syncthreads();
    int u = threadIdx.x;
    int r = u & 15, b0 = (u >> 4) * 2;
    int j = tile * 16 + r;
    if (j < Vc) {
        float s0 = bcls[j], s1 = bcls[j];
        #pragma unroll
        for (int kh = 0; kh < 8; kh++) {
            s0 += red[(kh * 16 + r) * 66 + b0];
            s1 += red[(kh * 16 + r) * 66 + b0 + 1];
        }
        outL[((size_t)b0 * Tc + t) * Vc + j]       = s0;
        outL[((size_t)(b0 + 1) * Tc + t) * Vc + j] = s1;
    }
}

// ---------------- weight preload ----------------
__device__ void preload_weights(float* sm, const float* __restrict__ Whh1,
                                const float* __restrict__ Whh2, const float* __restrict__ Wih2,
                                const float* __restrict__ W1, const float* __restrict__ Wemb) {
    int tid = threadIdx.x;
    int tile = blockIdx.x;
    if (tile < 64) {
        for (int i = tid; i < 32 * 128; i += NTHR) {
            int r = i >> 7, c4 = (i & 127) * 4;
            int srow = (r >> 3) * Hc + tile * 8 + (r & 7);
            *(float4*)&sm[OFF_W0 + r * 516 + c4] = *(const float4*)&Whh1[(size_t)srow * Hc + c4];
        }
    } else {
        int tl = tile - 64;
        for (int i = tid; i < 16 * 128; i += NTHR) {
            int r = i >> 7, c4 = (i & 127) * 4;
            int srow = tl * 16 + r; if (srow >= Vc) srow = Vc - 1;
            *(float4*)&sm[OFF_W0 + r * 516 + c4] = *(const float4*)&Wemb[(size_t)srow * Hc + c4];
        }
    }
    for (int i = tid; i < 16 * 128; i += NTHR) {
        int r = i >> 7, c4 = (i & 127) * 4;
        int srow = (r >> 2) * Hc + tile * 4 + (r & 3);
        *(float4*)&sm[OFF_WL2H + r * 516 + c4] = *(const float4*)&Whh2[(size_t)srow * Hc + c4];
        *(float4*)&sm[OFF_WL2X + r * 516 + c4] = *(const float4*)&Wih2[(size_t)srow * Hc + c4];
    }
    for (int i = tid; i < 4 * 256; i += NTHR) {
        int r = i >> 8, c4 = (i & 255) * 4;
        *(float4*)&sm[OFF_WHID + r * 1028 + c4] =
            *(const float4*)&W1[(size_t)(tile * 4 + r) * (Hc + Ec) + c4];
    }
}

// ---------------- precompute 64x64 GEMM tile ----------------
__device__ __forceinline__ void storeC(float* C, size_t idx, float v) { C[idx] = v; }
__device__ __forceinline__ void storeC(__half* C, size_t idx, float v) { C[idx] = __float2half(v); }

template<bool WT, class OUT>
__device__ void gemm_tile(const float* __restrict__ A, const float* __restrict__ W,
                          const float* __restrict__ b1v, const float* __restrict__ b2v,
                          OUT* __restrict__ C, int M, int N, int K, int m0, int n0, float* sm) {
    float* As = sm + OFF_AB;
    float* Ws = As + 16 * 68;
    int tid = threadIdx.x;
    int tx = tid & 15, ty = tid >> 4;
    float acc[2][4] = {};
    for (int kb = 0; kb < K; kb += 16) {
        __syncthreads();
        #pragma unroll
        for (int u2 = 0; u2 < 2; u2++) {
            int i = tid + u2 * NTHR;
            int r = i >> 4, kk = i & 15;
            int ra = m0 + r; if (ra >= M) ra = M - 1;
            As[kk * 68 + r] = A[(size_t)ra * K + kb + kk];
            Ws[kk * 68 + r] = WT ? W[(size_t)(kb + kk) * N + n0 + r]
                                 : W[(size_t)(n0 + r) * K + kb + kk];
        }
        __syncthreads();
        #pragma unroll
        for (int kk = 0; kk < 16; kk++) {
            float a0 = As[kk * 68 + ty * 2];
            float a1 = As[kk * 68 + ty * 2 + 1];
            float4 w4 = *(const float4*)&Ws[kk * 68 + tx * 4];
            float wr[4] = {w4.x, w4.y, w4.z, w4.w};
            #pragma unroll
            for (int jv = 0; jv < 4; jv++) {
                acc[0][jv] += a0 * wr[jv];
                acc[1][jv] += a1 * wr[jv];
            }
        }
    }
    __syncthreads();
    #pragma unroll
    for (int i = 0; i < 2; i++) {
        int row = m0 + ty * 2 + i;
        if (row < M) {
            #pragma unroll
            for (int jv = 0; jv < 4; jv++) {
                int col = n0 + tx * 4 + jv;
                float vv = acc[i][jv];
                if (b1v) vv += b1v[col];
                if (b2v) vv += b2v[col];
                storeC(C, (size_t)row * N + col, vv);
            }
        }
    }
}

// ---------------- persistent kernel ----------------
__global__ void __launch_bounds__(NTHR, 1)
decoder_kernel(const float* __restrict__ enc, const int* __restrict__ y,
               const float* __restrict__ Wemb,
               const float* __restrict__ Wih1, const float* __restrict__ bih1,
               const float* __restrict__ Whh1, const float* __restrict__ bhh1,
               const float* __restrict__ Wih2, const float* __restrict__ bih2,
               const float* __restrict__ Whh2, const float* __restrict__ bhh2,
               const float* __restrict__ Wq,  const float* __restrict__ bq,
               const float* __restrict__ Wk,  const float* __restrict__ bk,
               const float* __restrict__ Wv,  const float* __restrict__ bv,
               const float* __restrict__ W1,  const float* __restrict__ b1,
               const float* __restrict__ bcls,
               float* __restrict__ outL, float* __restrict__ attnB,
               int attnBS, int attnTS)
{
    extern __shared__ float sm[];
    int tid = threadIdx.x;
    unsigned gen = g_flags[blockIdx.x * 32];   // replay-safe base

    for (int i = blockIdx.x * NTHR + tid; i < BH; i += NBLK * NTHR) {
        g_h1P[i] = 0.f; g_c1T[i] = 0.f; g_h2P[i] = 0.f; g_c2T[i] = 0.f;
    }
    preload_weights(sm, Whh1, Whh2, Wih2, W1, Wemb);
    gsync(++gen);

    // pre1: K fp32 (temp), V fp16, LSTM1 token table
    {
        const int nKt = (Bc * Sc / 64) * (KQc / 64);
        const int nVt = (Bc * Sc / 64) * (Ec / 64);
        const int nEt = 16 * (4 * Hc / 64);
        for (int idx = blockIdx.x; idx < nKt + nVt + nEt; idx += NBLK) {
            if (idx < nKt) {
                int m0 = (idx / (KQc / 64)) * 64, n0 = (idx % (KQc / 64)) * 64;
                gemm_tile<false>(enc, Wk, bk, (const float*)0, g_ktmp,
                                 Bc * Sc, KQc, Ec, m0, n0, sm);
            } else if (idx < nKt + nVt) {
                int i2 = idx - nKt;
                int m0 = (i2 / (Ec / 64)) * 64, n0 = (i2 % (Ec / 64)) * 64;
                gemm_tile<false>(enc, Wv, bv, (const float*)0, g_vh,
                                 Bc * Sc, Ec, Ec, m0, n0, sm);
            } else {
                int i2 = idx - nKt - nVt;
                int m0 = (i2 / 32) * 64, n0 = (i2 % 32) * 64;
                gemm_tile<false>(Wemb, Wih1, bih1, bhh1, g_emb1,
                                 Vc, 4 * Hc, Hc, m0, n0, sm);
            }
        }
    }
    gsync(++gen);

    // pre2: KK = K @ Wq (fp16) and c0 = K . bq
    {
        const int nT = (Bc * Sc / 64) * (Ec / 64);
        for (int idx = blockIdx.x; idx < nT; idx += NBLK) {
            int m0 = (idx / (Ec / 64)) * 64, n0 = (idx % (Ec / 64)) * 64;
            gemm_tile<true>(g_ktmp, Wq, (const float*)0, (const float*)0, g_kk,
                            Bc * Sc, Ec, KQc, m0, n0, sm);
        }
        int lane = tid & 31;
        int gw = (blockIdx.x * NTHR + tid) >> 5;
        float bqr[8];
        #pragma unroll
        for (int q = 0; q < 8; q++) bqr[q] = bq[lane * 8 + q];
        for (int m = gw; m < Bc * Sc; m += (NBLK * NTHR) >> 5) {
            const float* kr = g_ktmp + (size_t)m * KQc + lane * 8;
            float4 k0 = *(const float4*)kr;
            float4 k1 = *(const float4*)(kr + 4);
            float s = bqr[0]*k0.x + bqr[1]*k0.y + bqr[2]*k0.z + bqr[3]*k0.w
                    + bqr[4]*k1.x + bqr[5]*k1.y + bqr[6]*k1.z + bqr[7]*k1.w;
            #pragma unroll
            for (int o = 16; o; o >>= 1) s += __shfl_down_sync(~0u, s, o);
            if (lane == 0) g_c0[m] = s;
        }
    }
    gsync(++gen);

    int pairb = blockIdx.x >> 1, half = blockIdx.x & 1;

    for (int t = 0; t < Tc; t++) {
        int cur = t & 1, nxt = cur ^ 1;

        // PA: LSTM1 (blocks 0..63) || logits(t-1) (blocks 64..127)
        if (blockIdx.x < 64)
            lstm1_phase(cur, nxt, y, t, sm);
        else if (t > 0)
            logits_phase(bcls, outL, t - 1, sm);
        gsync(++gen);

        // PB: LSTM2 (all blocks)
        lstm2_phase(cur, nxt, bih2, bhh2, sm);
        gsync(++gen);

        // PC: split-KV attention (all blocks; 2 per batch)
        {
            float* ah = attnB + (size_t)pairb * attnBS + (size_t)t * attnTS + half * 256;
            attn_phase(nxt, ah, sm);
        }
        gsync(++gen);

        // PD: merge + rescale attn + hid
        {
            float* ah = attnB + (size_t)pairb * attnBS + (size_t)t * attnTS + half * 256;
            hid_phase(nxt, b1, ah, sm);
        }
        gsync(++gen);
    }

    // final logits for t = Tc-1
    if (blockIdx.x >= 64)
        logits_phase(bcls, outL, Tc - 1, sm);
}

// ---------------- launch ----------------
extern "C" void kernel_launch(void* const* d_in, const int* in_sizes, int n_in,
                              void* d_out, int out_size) {
    const float* enc   = (const float*)d_in[0];
    const int*   y     = (const int*)  d_in[1];
    const float* Wemb  = (const float*)d_in[2];
    const float* Wih1  = (const float*)d_in[3];
    const float* bih1  = (const float*)d_in[4];
    const float* Whh1  = (const float*)d_in[5];
    const float* bhh1  = (const float*)d_in[6];
    const float* Wih2  = (const float*)d_in[7];
    const float* bih2  = (const float*)d_in[8];
    const float* Whh2  = (const float*)d_in[9];
    const float* bhh2  = (const float*)d_in[10];
    const float* Wq    = (const float*)d_in[11];
    const float* bq    = (const float*)d_in[12];
    const float* Wk    = (const float*)d_in[13];
    const float* bk    = (const float*)d_in[14];
    const float* Wv    = (const float*)d_in[15];
    const float* bv    = (const float*)d_in[16];
    const float* W1    = (const float*)d_in[17];
    const float* b1    = (const float*)d_in[18];
    const float* bcls  = (const float*)d_in[19];

    float* outL = (float*)d_out;
    long long need = (long long)Bc * Tc * Vc + (long long)Bc * Tc * Sc;

    float* attnB; int attnBS, attnTS;
    if ((long long)out_size >= need) {
        attnB = outL + (size_t)Bc * Tc * Vc;
        attnBS = Tc * Sc; attnTS = Sc;
    } else {
        cudaGetSymbolAddress((void**)&attnB, g_attn_dummy);
        attnBS = Sc; attnTS = 0;
    }

    cudaFuncSetAttribute(decoder_kernel,
                         cudaFuncAttributeMaxDynamicSharedMemorySize, SMEM_BYTES);

    decoder_kernel<<<NBLK, NTHR, SMEM_BYTES>>>(enc, y, Wemb, Wih1, bih1, Whh1, bhh1,
                                               Wih2, bih2, Whh2, bhh2, Wq, bq, Wk, bk,
                                               Wv, bv, W1, b1, bcls, outL,
                                               attnB, attnBS, attnTS);
}

// round 16
// speedup vs baseline: 1.0957x; 1.0118x over previous
#include <cuda_runtime.h>
#include <cuda_fp16.h>
#include <math.h>

#define Bc  64
#define Sc  512
#define Tc  256
#define Ec  512
#define Hc  512
#define KQc 256
#define Vc  1000
#define BH  (Bc*Hc)
#define NBLK 128
#define NTHR 512

typedef unsigned long long u64t;

// k-paired transposed activation index: aP[(j>>1)*128 + b*2 + (j&1)]
#define PIDX(j,b) ((((j)>>1)<<7) + ((b)<<1) + ((j)&1))

// ---------------- dynamic smem layout (float offsets) ----------------
#define OFF_W0    0                      // A-blocks: Whh1 32x516 ; B-blocks: Wemb 16x516
#define OFF_WL2H  16512                  // Whh2 16x516
#define OFF_WL2X  24768                  // Wih2 16x516
#define OFF_WHID  33024                  // W1 4x1028 (full K=1024)
#define OFF_AB    37136                  // attn struct + precompute tiles
#define OFF_RED   45840                  // reduction 128x66
#define OFF_SS    (OFF_RED + 8320)       // 128 merge scales
#define SMEM_F    54288
#define SMEM_BYTES (SMEM_F * 4)          // 217152 B

// ---------------- device scratch ----------------
__device__ float  g_ktmp[(size_t)Bc*Sc*KQc];   // K fp32 (precompute temp)
__device__ __half g_kk[(size_t)Bc*Sc*Ec];      // KK = K @ Wq  [B*S, 512] fp16
__device__ float  g_c0[(size_t)Bc*Sc];         // bq . k
__device__ __half g_vh[(size_t)Bc*Sc*Ec];      // V cache fp16
__device__ float  g_emb1[(size_t)Vc*4*Hc];     // token -> LSTM1 x-side gate preacts
__device__ __align__(16) float g_h1P[2*BH];    // h1 transposed k-paired, double-buffered
__device__ __align__(16) float g_h2P[2*BH];
__device__ __align__(16) float g_c1T[2*BH];    // c transposed [j][b]
__device__ __align__(16) float g_c2T[2*BH];
__device__ __align__(16) float g_hidP[BH];     // hid transposed k-paired
__device__ __align__(16) float g_ctxpP[2*(size_t)Bc*Ec];  // ctx partials k-paired [half]
__device__ float2 g_mz[2*Bc];                  // per (b,half): {m_local, Z_local}
__device__ float  g_attn_dummy[Bc*Sc];

// ---------------- grid barrier: all-poll (replay-safe) ----------------
__device__ volatile unsigned g_flags[NBLK*32];

__device__ __forceinline__ void gsync(unsigned gen) {
    __syncthreads();
    if (threadIdx.x == 0) {
        __threadfence();
        g_flags[blockIdx.x * 32] = gen;
    }
    if (threadIdx.x < NBLK) {
        while (g_flags[threadIdx.x * 32] < gen) { }
        __threadfence();
    }
    __syncthreads();
}

// ---------------- f32x2 packed FMA ----------------
__device__ __forceinline__ u64t fma2(u64t a, u64t b, u64t c) {
    u64t d;
    asm("fma.rn.f32x2 %0, %1, %2, %3;" : "=l"(d) : "l"(a), "l"(b), "l"(c));
    return d;
}
__device__ __forceinline__ float hsum2(u64t v) {
    return __uint_as_float((unsigned)v) + __uint_as_float((unsigned)(v >> 32));
}
__device__ __forceinline__ u64t pack2(float lo, float hi) {
    u64t d;
    asm("mov.b64 %0, {%1, %2};" : "=l"(d) : "r"(__float_as_uint(lo)), "r"(__float_as_uint(hi)));
    return d;
}
__device__ __forceinline__ u64t dup2(float x) { return pack2(x, x); }

// ---------------- unstaged GEMM core ----------------
// warp = (rg, kh): kh = warp % NKH, rg = warp / NKH; NKH = 16/(NROWS/NRPT).
// Thread covers W rows rg*NRPT..+NRPT-1 (BROADCAST smem loads) and batches
// (2*lane, 2*lane+1) via ONE LDG.128 per k-pair. k in [kh*KT, (kh+1)*KT).
template<int NROWS, int NRPT, int KTOT>
__device__ __forceinline__ void mm_unstaged(u64t (*acc)[2], const float* __restrict__ aP,
                                            const float* __restrict__ wsm, int padw) {
    const int NRG = NROWS / NRPT;
    const int NKH = 16 / NRG;
    const int KT = KTOT / NKH;
    int warp = threadIdx.x >> 5, lane = threadIdx.x & 31;
    int kh = warp % NKH, rg = warp / NKH;
    const float* wb = wsm + rg * NRPT * padw;
    const u64t* a64 = (const u64t*)aP;
    int k0 = kh * KT;
    #pragma unroll 8
    for (int kp = 0; kp < KT; kp += 2) {
        int k = k0 + kp;
        ulonglong2 av = *(const ulonglong2*)&a64[(k >> 1) * 64 + 2 * lane];
        #pragma unroll
        for (int r = 0; r < NRPT; r++) {
            u64t w2 = *(const u64t*)(wb + r * padw + k);
            acc[r][0] = fma2(av.x, w2, acc[r][0]);   // batch 2*lane
            acc[r][1] = fma2(av.y, w2, acc[r][1]);   // batch 2*lane+1
        }
    }
}

template<int NROWS, int NRPT>
__device__ __forceinline__ void red_writeU(u64t (*acc)[2], float* red) {
    const int NRG = NROWS / NRPT;
    const int NKH = 16 / NRG;
    int warp = threadIdx.x >> 5, lane = threadIdx.x & 31;
    int kh = warp % NKH, rg = warp / NKH;
    #pragma unroll
    for (int r = 0; r < NRPT; r++) {
        int rr = kh * NROWS + rg * NRPT + r;
        // batches (2*lane, 2*lane+1): one aligned STS.64, conflict-free
        *(u64t*)&red[rr * 66 + 2 * lane] = pack2(hsum2(acc[r][0]), hsum2(acc[r][1]));
    }
}

// ctx stream of hid: A = s0[b]*ctxp0 + s1[b]*ctxp1, W cols 512..1023 of W1 rows
__device__ void mm_ctx(u64t (*acc)[2], const float* __restrict__ wsm1028, float* sm) {
    const float* sS = sm + OFF_SS;
    int warp = threadIdx.x >> 5, lane = threadIdx.x & 31;
    // batches b0 = 2*lane, b1 = 2*lane+1; sS index = 2*b + half
    u64t s00 = dup2(sS[4 * lane]);
    u64t s01 = dup2(sS[4 * lane + 1]);
    u64t s10 = dup2(sS[4 * lane + 2]);
    u64t s11 = dup2(sS[4 * lane + 3]);
    const u64t* c0p = (const u64t*)g_ctxpP;
    const u64t* c1p = c0p + (BH >> 1);
    int e0 = warp * 32;
    #pragma unroll 4
    for (int ep = 0; ep < 32; ep += 2) {
        int e = e0 + ep;
        int idx = (e >> 1) * 64 + 2 * lane;
        ulonglong2 x0 = *(const ulonglong2*)&c0p[idx];
        ulonglong2 x1 = *(const ulonglong2*)&c1p[idx];
        u64t a0 = fma2(x1.x, s01, fma2(x0.x, s00, 0ull));
        u64t a1 = fma2(x1.y, s11, fma2(x0.y, s10, 0ull));
        #pragma unroll
        for (int r = 0; r < 4; r++) {
            u64t w2 = *(const u64t*)(wsm1028 + r * 1028 + 512 + e);
            acc[r][0] = fma2(a0, w2, acc[r][0]);
            acc[r][1] = fma2(a1, w2, acc[r][1]);
        }
    }
}

// ---------------- LSTM1: blocks 0..63, 32 rows (8 j) each ----------------
__device__ void lstm1_phase(int cur, int nxt, const int* __restrict__ y, int t, float* sm) {
    int tile = blockIdx.x;
    u64t acc[8][2] = {};
    mm_unstaged<32, 8, 512>(acc, g_h1P + cur * BH, sm + OFF_W0, 516);
    float* red = sm + OFF_RED;
    red_writeU<32, 8>(acc, red);
    __syncthreads();
    int u = threadIdx.x;
    int b = u & 63, jj = u >> 6;
    int j = tile * 8 + jj;
    float p[4] = {0.f, 0.f, 0.f, 0.f};
    #pragma unroll
    for (int kh = 0; kh < 4; kh++)
        #pragma unroll
        for (int g = 0; g < 4; g++)
            p[g] += red[(kh * 32 + g * 8 + jj) * 66 + b];
    int tok = (t == 0) ? 0 : y[b * Tc + t - 1];
    const float* e = g_emb1 + (size_t)tok * (4 * Hc);
    p[0] += e[j]; p[1] += e[Hc + j]; p[2] += e[2 * Hc + j]; p[3] += e[3 * Hc + j];
    float si = 1.f / (1.f + __expf(-p[0]));
    float sf = 1.f / (1.f + __expf(-p[1]));
    float so = 1.f / (1.f + __expf(-p[3]));
    float cN = sf * g_c1T[cur * BH + j * 64 + b] + si * tanhf(p[2]);
    float hN = so * tanhf(cN);
    g_h1P[nxt * BH + PIDX(j, b)] = hN;
    g_c1T[nxt * BH + j * 64 + b] = cN;
}

// ---------------- LSTM2: all blocks, 16 rows (4 j) ----------------
__device__ void lstm2_phase(int cur, int nxt,
                            const float* __restrict__ bih, const float* __restrict__ bhh,
                            float* sm) {
    int tile = blockIdx.x;
    u64t acc[8][2] = {};
    mm_unstaged<16, 8, 512>(acc, g_h2P + cur * BH, sm + OFF_WL2H, 516);
    mm_unstaged<16, 8, 512>(acc, g_h1P + nxt * BH, sm + OFF_WL2X, 516);
    float* red = sm + OFF_RED;
    red_writeU<16, 8>(acc, red);
    __syncthreads();
    int u = threadIdx.x;
    if (u < 256) {
        int b = u & 63, jj = u >> 6;
        int j = tile * 4 + jj;
        float p[4] = {0.f, 0.f, 0.f, 0.f};
        #pragma unroll
        for (int kh = 0; kh < 8; kh++)
            #pragma unroll
            for (int g = 0; g < 4; g++)
                p[g] += red[(kh * 16 + g * 4 + jj) * 66 + b];
        p[0] += bih[j]          + bhh[j];
        p[1] += bih[Hc + j]     + bhh[Hc + j];
        p[2] += bih[2 * Hc + j] + bhh[2 * Hc + j];
        p[3] += bih[3 * Hc + j] + bhh[3 * Hc + j];
        float si = 1.f / (1.f + __expf(-p[0]));
        float sf = 1.f / (1.f + __expf(-p[1]));
        float so = 1.f / (1.f + __expf(-p[3]));
        float cN = sf * g_c2T[cur * BH + j * 64 + b] + si * tanhf(p[2]);
        float hN = so * tanhf(cN);
        g_h2P[nxt * BH + PIDX(j, b)] = hN;
        g_c2T[nxt * BH + j * 64 + b] = cN;
    }
}

// ---------------- attention: split-KV, 2 blocks per batch ----------------
struct AttnS {
    float qh[512];
    float scl[256];
    float ctxp[3 * 512];
    float red[16];
    float red2[16];
};

__device__ __forceinline__ float dot8h(const float* qr, uint4 pk) {
    const __half2* p2 = (const __half2*)&pk;
    float s = 0.f;
    #pragma unroll
    for (int q = 0; q < 4; q++) {
        float2 f = __half22float2(p2[q]);
        s += qr[q * 2] * f.x + qr[q * 2 + 1] * f.y;
    }
    return s;
}

__device__ void attn_phase(int nxt, float* __restrict__ attn_half, float* sm) {
    int pairb = blockIdx.x >> 1, half = blockIdx.x & 1;
    AttnS* at = (AttnS*)(sm + OFF_AB);
    int tid = threadIdx.x, warp = tid >> 5, lane = tid & 31;
    int s0 = half * 256;

    at->qh[tid] = g_h2P[nxt * BH + PIDX(tid, pairb)];
    __syncthreads();

    float hr[16];
    #pragma unroll
    for (int q = 0; q < 4; q++) {
        float4 f = *(const float4*)&at->qh[lane * 16 + q * 4];
        hr[q * 4 + 0] = f.x; hr[q * 4 + 1] = f.y;
        hr[q * 4 + 2] = f.z; hr[q * 4 + 3] = f.w;
    }

    // scores: sc = (h2 . KK[b,s] + c0[b,s]) * scale
    #pragma unroll
    for (int i = 0; i < 8; i++) {
        int sA = s0 + warp + i * 32, sB = sA + 16;
        const __half* ka = g_kk + ((size_t)(pairb * Sc + sA)) * Ec + lane * 16;
        const __half* kb = g_kk + ((size_t)(pairb * Sc + sB)) * Ec + lane * 16;
        float sa = dot8h(hr, *(const uint4*)ka) + dot8h(hr + 8, *(const uint4*)(ka + 8));
        float sb = dot8h(hr, *(const uint4*)kb) + dot8h(hr + 8, *(const uint4*)(kb + 8));
        #pragma unroll
        for (int o = 16; o; o >>= 1) {
            sa += __shfl_down_sync(~0u, sa, o);
            sb += __shfl_down_sync(~0u, sb, o);
        }
        if (lane == 0) {
            at->scl[sA - s0] = (sa + g_c0[pairb * Sc + sA]) * 0.0625f;
            at->scl[sB - s0] = (sb + g_c0[pairb * Sc + sB]) * 0.0625f;
        }
    }
    __syncthreads();

    // local softmax partials over 256
    float v = (tid < 256) ? at->scl[tid] : -3.0e38f;
    float m = v;
    #pragma unroll
    for (int o = 16; o; o >>= 1) m = fmaxf(m, __shfl_xor_sync(~0u, m, o));
    if (lane == 0) at->red[warp] = m;
    __syncthreads();
    float mm = at->red[0];
    #pragma unroll
    for (int w = 1; w < 8; w++) mm = fmaxf(mm, at->red[w]);
    float e = (tid < 256) ? __expf(v - mm) : 0.f;
    float ssum = e;
    #pragma unroll
    for (int o = 16; o; o >>= 1) ssum += __shfl_xor_sync(~0u, ssum, o);
    if (lane == 0) at->red2[warp] = ssum;
    __syncthreads();
    if (tid == 0) {
        float Z = 0.f;
        #pragma unroll
        for (int w = 0; w < 16; w++) Z += at->red2[w];
        g_mz[pairb * 2 + half] = make_float2(mm, Z);
    }
    if (tid < 256) {
        at->scl[tid] = e;
        attn_half[tid] = e;              // unnormalized; rescaled in PD
    }
    __syncthreads();

    // partial ctx over this half (fp16 V), 4-way s-split
    int sq = tid >> 7;
    int e4 = (tid & 127) * 4;
    const __half* vb = g_vh + (size_t)pairb * Sc * Ec + e4;
    float a0 = 0.f, a1 = 0.f, a2 = 0.f, a3 = 0.f;
    int sb2 = sq * 64;
    #pragma unroll 8
    for (int i2 = 0; i2 < 64; i2++) {
        float pp = at->scl[sb2 + i2];
        uint2 pk = *(const uint2*)(vb + (size_t)(s0 + sb2 + i2) * Ec);
        float2 f0 = __half22float2(*(__half2*)&pk.x);
        float2 f1 = __half22float2(*(__half2*)&pk.y);
        a0 += pp * f0.x; a1 += pp * f0.y; a2 += pp * f1.x; a3 += pp * f1.y;
    }
    if (sq) {
        float* cp = at->ctxp + (sq - 1) * 512 + e4;
        cp[0] = a0; cp[1] = a1; cp[2] = a2; cp[3] = a3;
    }
    __syncthreads();
    if (sq == 0) {
        #pragma unroll
        for (int q = 0; q < 3; q++) {
            const float* cp = at->ctxp + q * 512 + e4;
            a0 += cp[0]; a1 += cp[1]; a2 += cp[2]; a3 += cp[3];
        }
        u64t* gp = (u64t*)(g_ctxpP + (size_t)half * BH);
        gp[(e4 >> 1) * 64 + pairb]       = pack2(a0, a1);
        gp[((e4 + 2) >> 1) * 64 + pairb] = pack2(a2, a3);
    }
}

// ---------------- hid: merge scales + rescale attn + hid GEMM ----------------
__device__ void hid_phase(int nxt, const float* __restrict__ b1,
                          float* __restrict__ attn_half, float* sm) {
    float* sS = sm + OFF_SS;
    int tid = threadIdx.x;
    if (tid < 128) {
        int bb = tid >> 1, h = tid & 1;
        float2 mz0 = g_mz[bb * 2 + 0];
        float2 mz1 = g_mz[bb * 2 + 1];
        float m = fmaxf(mz0.x, mz1.x);
        float Z = mz0.y * __expf(mz0.x - m) + mz1.y * __expf(mz1.x - m);
        float mh = h ? mz1.x : mz0.x;
        sS[tid] = __expf(mh - m) / Z;
    }
    __syncthreads();
    {
        float f = sS[blockIdx.x];
        if (tid < 256) attn_half[tid] *= f;
    }
    u64t acc[4][2] = {};
    mm_unstaged<4, 4, 512>(acc, g_h2P + nxt * BH, sm + OFF_WHID, 1028);
    mm_ctx(acc, sm + OFF_WHID, sm);
    float* red = sm + OFF_RED;
    red_writeU<4, 4>(acc, red);
    __syncthreads();
    int u = threadIdx.x;
    if (u < 256) {
        int b = u & 63, r = u >> 6;
        int j = blockIdx.x * 4 + r;
        float sum = b1[j];
        #pragma unroll
        for (int kh = 0; kh < 16; kh++) sum += red[(kh * 4 + r) * 66 + b];
        g_hidP[PIDX(j, b)] = fmaxf(sum, 0.f);
    }
}

// ---------------- logits: B-blocks, 16 rows each ----------------
__device__ void logits_phase(const float* __restrict__ bcls, float* __restrict__ outL,
                             int t, float* sm) {
    int tile = blockIdx.x - 64;
    u64t acc[8][2] = {};
    mm_unstaged<16, 8, 512>(acc, g_hidP, sm + OFF_W0, 516);
    float* red = sm + OFF_RED;
    red_writeU<16, 8>(acc, red);
    __syncthreads();
    int u = threadIdx.x;
    int r = u & 15, b0 = (u >> 4) * 2;
    int j = tile * 16 + r;
    if (j < Vc) {
        float s0 = bcls[j], s1 = bcls[j];
        #pragma unroll
        for (int kh = 0; kh < 8; kh++) {
            s0 += red[(kh * 16 + r) * 66 + b0];
            s1 += red[(kh * 16 + r) * 66 + b0 + 1];
        }
        outL[((size_t)b0 * Tc + t) * Vc + j]       = s0;
        outL[((size_t)(b0 + 1) * Tc + t) * Vc + j] = s1;
    }
}

// ---------------- weight preload ----------------
__device__ void preload_weights(float* sm, const float* __restrict__ Whh1,
                                const float* __restrict__ Whh2, const float* __restrict__ Wih2,
                                const float* __restrict__ W1, const float* __restrict__ Wemb) {
    int tid = threadIdx.x;
    int tile = blockIdx.x;
    if (tile < 64) {
        for (int i = tid; i < 32 * 128; i += NTHR) {
            int r = i >> 7, c4 = (i & 127) * 4;
            int srow = (r >> 3) * Hc + tile * 8 + (r & 7);
            *(float4*)&sm[OFF_W0 + r * 516 + c4] = *(const float4*)&Whh1[(size_t)srow * Hc + c4];
        }
    } else {
        int tl = tile - 64;
        for (int i = tid; i < 16 * 128; i += NTHR) {
            int r = i >> 7, c4 = (i & 127) * 4;
            int srow = tl * 16 + r; if (srow >= Vc) srow = Vc - 1;
            *(float4*)&sm[OFF_W0 + r * 516 + c4] = *(const float4*)&Wemb[(size_t)srow * Hc + c4];
        }
    }
    for (int i = tid; i < 16 * 128; i += NTHR) {
        int r = i >> 7, c4 = (i & 127) * 4;
        int srow = (r >> 2) * Hc + tile * 4 + (r & 3);
        *(float4*)&sm[OFF_WL2H + r * 516 + c4] = *(const float4*)&Whh2[(size_t)srow * Hc + c4];
        *(float4*)&sm[OFF_WL2X + r * 516 + c4] = *(const float4*)&Wih2[(size_t)srow * Hc + c4];
    }
    for (int i = tid; i < 4 * 256; i += NTHR) {
        int r = i >> 8, c4 = (i & 255) * 4;
        *(float4*)&sm[OFF_WHID + r * 1028 + c4] =
            *(const float4*)&W1[(size_t)(tile * 4 + r) * (Hc + Ec) + c4];
    }
}

// ---------------- precompute 64x64 GEMM tile ----------------
__device__ __forceinline__ void storeC(float* C, size_t idx, float v) { C[idx] = v; }
__device__ __forceinline__ void storeC(__half* C, size_t idx, float v) { C[idx] = __float2half(v); }

template<bool WT, class OUT>
__device__ void gemm_tile(const float* __restrict__ A, const float* __restrict__ W,
                          const float* __restrict__ b1v, const float* __restrict__ b2v,
                          OUT* __restrict__ C, int M, int N, int K, int m0, int n0, float* sm) {
    float* As = sm + OFF_AB;
    float* Ws = As + 16 * 68;
    int tid = threadIdx.x;
    int tx = tid & 15, ty = tid >> 4;
    float acc[2][4] = {};
    for (int kb = 0; kb < K; kb += 16) {
        __syncthreads();
        #pragma unroll
        for (int u2 = 0; u2 < 2; u2++) {
            int i = tid + u2 * NTHR;
            int r = i >> 4, kk = i & 15;
            int ra = m0 + r; if (ra >= M) ra = M - 1;
            As[kk * 68 + r] = A[(size_t)ra * K + kb + kk];
            Ws[kk * 68 + r] = WT ? W[(size_t)(kb + kk) * N + n0 + r]
                                 : W[(size_t)(n0 + r) * K + kb + kk];
        }
        __syncthreads();
        #pragma unroll
        for (int kk = 0; kk < 16; kk++) {
            float a0 = As[kk * 68 + ty * 2];
            float a1 = As[kk * 68 + ty * 2 + 1];
            float4 w4 = *(const float4*)&Ws[kk * 68 + tx * 4];
            float wr[4] = {w4.x, w4.y, w4.z, w4.w};
            #pragma unroll
            for (int jv = 0; jv < 4; jv++) {
                acc[0][jv] += a0 * wr[jv];
                acc[1][jv] += a1 * wr[jv];
            }
        }
    }
    __syncthreads();
    #pragma unroll
    for (int i = 0; i < 2; i++) {
        int row = m0 + ty * 2 + i;
        if (row < M) {
            #pragma unroll
            for (int jv = 0; jv < 4; jv++) {
                int col = n0 + tx * 4 + jv;
                float vv = acc[i][jv];
                if (b1v) vv += b1v[col];
                if (b2v) vv += b2v[col];
                storeC(C, (size_t)row * N + col, vv);
            }
        }
    }
}

// ---------------- persistent kernel ----------------
__global__ void __launch_bounds__(NTHR, 1)
decoder_kernel(const float* __restrict__ enc, const int* __restrict__ y,
               const float* __restrict__ Wemb,
               const float* __restrict__ Wih1, const float* __restrict__ bih1,
               const float* __restrict__ Whh1, const float* __restrict__ bhh1,
               const float* __restrict__ Wih2, const float* __restrict__ bih2,
               const float* __restrict__ Whh2, const float* __restrict__ bhh2,
               const float* __restrict__ Wq,  const float* __restrict__ bq,
               const float* __restrict__ Wk,  const float* __restrict__ bk,
               const float* __restrict__ Wv,  const float* __restrict__ bv,
               const float* __restrict__ W1,  const float* __restrict__ b1,
               const float* __restrict__ bcls,
               float* __restrict__ outL, float* __restrict__ attnB,
               int attnBS, int attnTS)
{
    extern __shared__ float sm[];
    int tid = threadIdx.x;
    unsigned gen = g_flags[blockIdx.x * 32];   // replay-safe base

    for (int i = blockIdx.x * NTHR + tid; i < BH; i += NBLK * NTHR) {
        g_h1P[i] = 0.f; g_c1T[i] = 0.f; g_h2P[i] = 0.f; g_c2T[i] = 0.f;
    }
    preload_weights(sm, Whh1, Whh2, Wih2, W1, Wemb);
    gsync(++gen);

    // pre1: K fp32 (temp), V fp16, LSTM1 token table
    {
        const int nKt = (Bc * Sc / 64) * (KQc / 64);
        const int nVt = (Bc * Sc / 64) * (Ec / 64);
        const int nEt = 16 * (4 * Hc / 64);
        for (int idx = blockIdx.x; idx < nKt + nVt + nEt; idx += NBLK) {
            if (idx < nKt) {
                int m0 = (idx / (KQc / 64)) * 64, n0 = (idx % (KQc / 64)) * 64;
                gemm_tile<false>(enc, Wk, bk, (const float*)0, g_ktmp,
                                 Bc * Sc, KQc, Ec, m0, n0, sm);
            } else if (idx < nKt + nVt) {
                int i2 = idx - nKt;
                int m0 = (i2 / (Ec / 64)) * 64, n0 = (i2 % (Ec / 64)) * 64;
                gemm_tile<false>(enc, Wv, bv, (const float*)0, g_vh,
                                 Bc * Sc, Ec, Ec, m0, n0, sm);
            } else {
                int i2 = idx - nKt - nVt;
                int m0 = (i2 / 32) * 64, n0 = (i2 % 32) * 64;
                gemm_tile<false>(Wemb, Wih1, bih1, bhh1, g_emb1,
                                 Vc, 4 * Hc, Hc, m0, n0, sm);
            }
        }
    }
    gsync(++gen);

    // pre2: KK = K @ Wq (fp16) and c0 = K . bq
    {
        const int nT = (Bc * Sc / 64) * (Ec / 64);
        for (int idx = blockIdx.x; idx < nT; idx += NBLK) {
            int m0 = (idx / (Ec / 64)) * 64, n0 = (idx % (Ec / 64)) * 64;
            gemm_tile<true>(g_ktmp, Wq, (const float*)0, (const float*)0, g_kk,
                            Bc * Sc, Ec, KQc, m0, n0, sm);
        }
        int lane = tid & 31;
        int gw = (blockIdx.x * NTHR + tid) >> 5;
        float bqr[8];
        #pragma unroll
        for (int q = 0; q < 8; q++) bqr[q] = bq[lane * 8 + q];
        for (int m = gw; m < Bc * Sc; m += (NBLK * NTHR) >> 5) {
            const float* kr = g_ktmp + (size_t)m * KQc + lane * 8;
            float4 k0 = *(const float4*)kr;
            float4 k1 = *(const float4*)(kr + 4);
            float s = bqr[0]*k0.x + bqr[1]*k0.y + bqr[2]*k0.z + bqr[3]*k0.w
                    + bqr[4]*k1.x + bqr[5]*k1.y + bqr[6]*k1.z + bqr[7]*k1.w;
            #pragma unroll
            for (int o = 16; o; o >>= 1) s += __shfl_down_sync(~0u, s, o);
            if (lane == 0) g_c0[m] = s;
        }
    }
    gsync(++gen);

    int pairb = blockIdx.x >> 1, half = blockIdx.x & 1;

    for (int t = 0; t < Tc; t++) {
        int cur = t & 1, nxt = cur ^ 1;

        // PA: LSTM1 (blocks 0..63) || logits(t-1) (blocks 64..127)
        if (blockIdx.x < 64)
            lstm1_phase(cur, nxt, y, t, sm);
        else if (t > 0)
            logits_phase(bcls, outL, t - 1, sm);
        gsync(++gen);

        // PB: LSTM2 (all blocks)
        lstm2_phase(cur, nxt, bih2, bhh2, sm);
        gsync(++gen);

        // PC: split-KV attention (all blocks; 2 per batch)
        {
            float* ah = attnB + (size_t)pairb * attnBS + (size_t)t * attnTS + half * 256;
            attn_phase(nxt, ah, sm);
        }
        gsync(++gen);

        // PD: merge + rescale attn + hid
        {
            float* ah = attnB + (size_t)pairb * attnBS + (size_t)t * attnTS + half * 256;
            hid_phase(nxt, b1, ah, sm);
        }
        gsync(++gen);
    }

    // final logits for t = Tc-1
    if (blockIdx.x >= 64)
        logits_phase(bcls, outL, Tc - 1, sm);
}

// ---------------- launch ----------------
extern "C" void kernel_launch(void* const* d_in, const int* in_sizes, int n_in,
                              void* d_out, int out_size) {
    const float* enc   = (const float*)d_in[0];
    const int*   y     = (const int*)  d_in[1];
    const float* Wemb  = (const float*)d_in[2];
    const float* Wih1  = (const float*)d_in[3];
    const float* bih1  = (const float*)d_in[4];
    const float* Whh1  = (const float*)d_in[5];
    const float* bhh1  = (const float*)d_in[6];
    const float* Wih2  = (const float*)d_in[7];
    const float* bih2  = (const float*)d_in[8];
    const float* Whh2  = (const float*)d_in[9];
    const float* bhh2  = (const float*)d_in[10];
    const float* Wq    = (const float*)d_in[11];
    const float* bq    = (const float*)d_in[12];
    const float* Wk    = (const float*)d_in[13];
    const float* bk    = (const float*)d_in[14];
    const float* Wv    = (const float*)d_in[15];
    const float* bv    = (const float*)d_in[16];
    const float* W1    = (const float*)d_in[17];
    const float* b1    = (const float*)d_in[18];
    const float* bcls  = (const float*)d_in[19];

    float* outL = (float*)d_out;
    long long need = (long long)Bc * Tc * Vc + (long long)Bc * Tc * Sc;

    float* attnB; int attnBS, attnTS;
    if ((long long)out_size >= need) {
        attnB = outL + (size_t)Bc * Tc * Vc;
        attnBS = Tc * Sc; attnTS = Sc;
    } else {
        cudaGetSymbolAddress((void**)&attnB, g_attn_dummy);
        attnBS = Sc; attnTS = 0;
    }

    cudaFuncSetAttribute(decoder_kernel,
                         cudaFuncAttributeMaxDynamicSharedMemorySize, SMEM_BYTES);

    decoder_kernel<<<NBLK, NTHR, SMEM_BYTES>>>(enc, y, Wemb, Wih1, bih1, Whh1, bhh1,
                                               Wih2, bih2, Whh2, bhh2, Wq, bq, Wk, bk,
                                               Wv, bv, W1, b1, bcls, outL,
                                               attnB, attnBS, attnTS);
}